// round 3
// baseline (speedup 1.0000x reference)
#include <cuda_runtime.h>
#include <cstdint>

#define T_LEN   1048576
#define KSTEPS  512
#define NSLOTS  4
#define NCHUNK  (T_LEN / KSTEPS)

// shared memory layout (bytes)
#define OFF_PF   0                         // p_full[4]   (8B each)
#define OFF_PC   32                        // p_cons[4]
#define OFF_WF   64                        // w_full[4]
#define OFF_WE   96                        // w_free[4]
#define OFF_P    256                       // p ring: 4 slots x 512 steps x 64B
#define PSLOT    (KSTEPS * 64)
#define OFF_W    (OFF_P + NSLOTS * PSLOT)  // w ring: 4 slots x 512 steps x 32B
#define WSLOT    (KSTEPS * 32)
#define SMEM_SZ  (OFF_W + NSLOTS * WSLOT)  // 196864 bytes

typedef unsigned long long ull;
typedef unsigned int u32;

__device__ __forceinline__ void mbar_init(u32 a, u32 cnt) {
    asm volatile("mbarrier.init.shared.b64 [%0], %1;" :: "r"(a), "r"(cnt) : "memory");
}
__device__ __forceinline__ void mbar_arrive(u32 a) {
    asm volatile("mbarrier.arrive.release.cta.shared::cta.b64 _, [%0];" :: "r"(a) : "memory");
}
__device__ __forceinline__ void mbar_wait(u32 a, u32 par) {
    u32 done;
    asm volatile(
        "{\n\t.reg .pred p;\n\t"
        "mbarrier.try_wait.parity.acquire.cta.shared::cta.b64 p, [%1], %2;\n\t"
        "selp.b32 %0, 1, 0, p;\n\t}"
        : "=r"(done) : "r"(a), "r"(par) : "memory");
    if (!done) {
        asm volatile(
            "{\n\t.reg .pred P1;\n\t"
            "WL_%=:\n\t"
            "mbarrier.try_wait.parity.acquire.cta.shared::cta.b64 P1, [%0], %1, 0x989680;\n\t"
            "@P1 bra.uni WD_%=;\n\t"
            "bra.uni WL_%=;\n\t"
            "WD_%=:\n\t}"
            :: "r"(a), "r"(par) : "memory");
    }
}

// packed f32x2 add: bit-exact two IEEE rn f32 adds in one instruction.
// NON-volatile, no memory clobber: pure value ops the compiler may schedule freely.
__device__ __forceinline__ ull addx2(ull a, ull b) {
    ull r; asm("add.rn.f32x2 %0, %1, %2;" : "=l"(r) : "l"(a), "l"(b)); return r;
}
__device__ __forceinline__ float f2lo(ull v) {
    float f; asm("{ .reg .b32 h; mov.b64 {%0, h}, %1; }" : "=f"(f) : "l"(v)); return f;
}
__device__ __forceinline__ float f2hi(ull v) {
    float f; asm("{ .reg .b32 l; mov.b64 {l, %0}, %1; }" : "=f"(f) : "l"(v)); return f;
}
__device__ __forceinline__ ull fpack(float x, float y) {
    ull r; asm("mov.b64 %0, {%1, %2};" : "=l"(r) : "f"(x), "f"(y)); return r;
}

__global__ void __launch_bounds__(352, 1)
va_main(const float* __restrict__ y, const float* __restrict__ sp, float* __restrict__ out)
{
    extern __shared__ char smem[];
    u32 sb = (u32)__cvta_generic_to_shared(smem);
    int tid = threadIdx.x, wid = tid >> 5, lane = tid & 31;

    if (tid == 0) {
        for (int s = 0; s < NSLOTS; s++) {
            mbar_init(sb + OFF_PF + 8 * s, 64); // 64 fetch lanes arrive
            mbar_init(sb + OFF_PC + 8 * s, 1);  // producer arrives
            mbar_init(sb + OFF_WF + 8 * s, 1);  // producer arrives
            mbar_init(sb + OFF_WE + 8 * s, 8);  // 8 bit-warp leaders arrive
        }
    }
    __syncthreads();

    if (wid == 0) {
        // ---------------- serial Viterbi producer (single lane) ----------------
        if (lane == 0) {
            // packed state pairs {w0,w1},{w2,w3},{w4,w5},{w6,w7}; v0 = zeros
            ull w01 = 0ull, w23 = 0ull, w45 = 0ull, w67 = 0ull;
            for (int c = 0; c < NCHUNK; c++) {
                int s = c & 3;
                mbar_wait(sb + OFF_PF + 8 * s, (c >> 2) & 1);
                if (c >= NSLOTS) mbar_wait(sb + OFF_WE + 8 * s, ((c - NSLOTS) >> 2) & 1);
                // plain C++ smem accesses: schedulable / pipelinable by ptxas.
                const ulonglong2* __restrict__ pp =
                    (const ulonglong2*)(smem + OFF_P + s * PSLOT);   // 4 per step
                ulonglong2* __restrict__ wp =
                    (ulonglong2*)(smem + OFF_W + s * WSLOT);         // 2 per step
                #pragma unroll 8
                for (int k = 0; k < KSTEPS; k++) {
                    ulonglong2 q0 = pp[4 * k + 0];   // p0,p1
                    ulonglong2 q1 = pp[4 * k + 1];   // p2,p3
                    ulonglong2 q2 = pp[4 * k + 2];   // p4,p5
                    ulonglong2 q3 = pp[4 * k + 3];   // p6,p7
                    // m[u] = w[u&7] + p[u], packed two-at-a-time
                    ull m0 = addx2(w01, q0.x), m1 = addx2(w23, q0.y);
                    ull m2 = addx2(w45, q1.x), m3 = addx2(w67, q1.y);
                    ull m4 = addx2(w01, q2.x), m5 = addx2(w23, q2.y);
                    ull m6 = addx2(w45, q3.x), m7 = addx2(w67, q3.y);
                    // out[q] = min(m[2q], m[2q+1])  (horizontal within pair)
                    float o0 = fminf(f2lo(m0), f2hi(m0));
                    float o1 = fminf(f2lo(m1), f2hi(m1));
                    float o2 = fminf(f2lo(m2), f2hi(m2));
                    float o3 = fminf(f2lo(m3), f2hi(m3));
                    float o4 = fminf(f2lo(m4), f2hi(m4));
                    float o5 = fminf(f2lo(m5), f2hi(m5));
                    float o6 = fminf(f2lo(m6), f2hi(m6));
                    float o7 = fminf(f2lo(m7), f2hi(m7));
                    w01 = fpack(o0, o1); w23 = fpack(o2, o3);
                    w45 = fpack(o4, o5); w67 = fpack(o6, o7);
                    wp[2 * k + 0] = make_ulonglong2(w01, w23);
                    wp[2 * k + 1] = make_ulonglong2(w45, w67);
                }
                mbar_arrive(sb + OFF_PC + 8 * s);
                mbar_arrive(sb + OFF_WF + 8 * s);
            }
        }
    } else if (wid <= 2) {
        // ---------------- branch-metric producers: p[t][u] = |y[t] - sp[u]| ----
        int base = (wid - 1) * 32 + lane;   // 0..63
        int quad = base & 3;                // fixed 4-state group per lane
        float s0 = sp[quad * 4 + 0], s1 = sp[quad * 4 + 1];
        float s2 = sp[quad * 4 + 2], s3 = sp[quad * 4 + 3];
        for (int c = 0; c < NCHUNK; c++) {
            int s = c & 3;
            if (c >= NSLOTS) mbar_wait(sb + OFF_PC + 8 * s, ((c - NSLOTS) >> 2) & 1);
            float4* __restrict__ pb = (float4*)(smem + OFF_P + s * PSLOT);
            const float* yc = y + c * KSTEPS;
            #pragma unroll 4
            for (int it = 0; it < 32; it++) {
                int idx = it * 64 + base;
                int k = idx >> 2;           // step within chunk
                float yv = __ldg(&yc[k]);
                pb[k * 4 + quad] = make_float4(fabsf(yv - s0), fabsf(yv - s1),
                                               fabsf(yv - s2), fabsf(yv - s3));
            }
            mbar_arrive(sb + OFF_PF + 8 * s);
        }
    } else {
        // ---------------- bit extractors: bit[t] = argmin(w_t) % 2 -------------
        int btid = tid - 96;                // 0..255
        if (btid == 0) out[0] = 0.0f;       // v_0 = zeros -> argmin = 0 -> bit 0
        const float4* wr = (const float4*)(smem + OFF_W);
        for (int c = 0; c < NCHUNK; c++) {
            int s = c & 3;
            mbar_wait(sb + OFF_WF + 8 * s, (c >> 2) & 1);
            #pragma unroll
            for (int r = 0; r < 2; r++) {
                int k = r * 256 + btid;
                int i = c * KSTEPS + k;     // producer step index; W[i] = w_{i+1}
                if (i != T_LEN - 1) {
                    const float4* p = wr + (size_t)(s * KSTEPS + k) * 2;
                    float4 a = p[0], b = p[1];
                    // first-index argmin over 8 (strict < keeps lowest index,
                    // matching jnp.argmin tie-breaking; w[s]==w[s+8] so 8 suffice)
                    float best = a.x; int bi = 0;
                    if (a.y < best) { best = a.y; bi = 1; }
                    if (a.z < best) { best = a.z; bi = 2; }
                    if (a.w < best) { best = a.w; bi = 3; }
                    if (b.x < best) { best = b.x; bi = 4; }
                    if (b.y < best) { best = b.y; bi = 5; }
                    if (b.z < best) { best = b.z; bi = 6; }
                    if (b.w < best) {            bi = 7; }
                    out[i + 1] = (float)(bi & 1);
                }
            }
            __syncwarp();
            if (lane == 0) mbar_arrive(sb + OFF_WE + 8 * s);
        }
    }
}

extern "C" void kernel_launch(void* const* d_in, const int* in_sizes, int n_in,
                              void* d_out, int out_size)
{
    const float* a = (const float*)d_in[0];
    const float* b = (const float*)d_in[1];
    const float* y;
    const float* sp;
    if (in_sizes[0] == 16) { sp = a; y = b; }
    else                   { y = a;  sp = b; }

    cudaFuncSetAttribute(va_main, cudaFuncAttributeMaxDynamicSharedMemorySize, SMEM_SZ);
    va_main<<<1, 352, SMEM_SZ>>>(y, sp, (float*)d_out);
}

// round 4
// speedup vs baseline: 1.3845x; 1.3845x over previous
#include <cuda_runtime.h>
#include <cstdint>

#define T_LEN   1048576
#define KSTEPS  512
#define NSLOTS  4
#define NCHUNK  (T_LEN / KSTEPS)

// shared memory layout (bytes)
#define OFF_PF   0                         // p_full[4]   (8B each)
#define OFF_PC   32                        // p_cons[4]
#define OFF_WF   64                        // w_full[4]
#define OFF_WE   96                        // w_free[4]
#define OFF_P    256                       // p ring: 4 slots x 512 steps x 64B
#define PSLOT    (KSTEPS * 64)
#define OFF_W    (OFF_P + NSLOTS * PSLOT)  // w ring: 4 slots x 512 steps x 32B
#define WSLOT    (KSTEPS * 32)
#define SMEM_SZ  (OFF_W + NSLOTS * WSLOT + 128)  // +128 pad for prefetch overrun

typedef unsigned long long ull;
typedef unsigned int u32;

__device__ __forceinline__ void mbar_init(u32 a, u32 cnt) {
    asm volatile("mbarrier.init.shared.b64 [%0], %1;" :: "r"(a), "r"(cnt) : "memory");
}
__device__ __forceinline__ void mbar_arrive(u32 a) {
    asm volatile("mbarrier.arrive.release.cta.shared::cta.b64 _, [%0];" :: "r"(a) : "memory");
}
__device__ __forceinline__ void mbar_wait(u32 a, u32 par) {
    u32 done;
    asm volatile(
        "{\n\t.reg .pred p;\n\t"
        "mbarrier.try_wait.parity.acquire.cta.shared::cta.b64 p, [%1], %2;\n\t"
        "selp.b32 %0, 1, 0, p;\n\t}"
        : "=r"(done) : "r"(a), "r"(par) : "memory");
    if (!done) {
        asm volatile(
            "{\n\t.reg .pred P1;\n\t"
            "WL_%=:\n\t"
            "mbarrier.try_wait.parity.acquire.cta.shared::cta.b64 P1, [%0], %1, 0x989680;\n\t"
            "@P1 bra.uni WD_%=;\n\t"
            "bra.uni WL_%=;\n\t"
            "WD_%=:\n\t}"
            :: "r"(a), "r"(par) : "memory");
    }
}

// packed f32x2 add: bit-exact two IEEE rn f32 adds in one instruction.
__device__ __forceinline__ ull addx2(ull a, ull b) {
    ull r; asm("add.rn.f32x2 %0, %1, %2;" : "=l"(r) : "l"(a), "l"(b)); return r;
}
__device__ __forceinline__ float f2lo(ull v) {
    float f; asm("{ .reg .b32 h; mov.b64 {%0, h}, %1; }" : "=f"(f) : "l"(v)); return f;
}
__device__ __forceinline__ float f2hi(ull v) {
    float f; asm("{ .reg .b32 l; mov.b64 {l, %0}, %1; }" : "=f"(f) : "l"(v)); return f;
}
__device__ __forceinline__ ull fpack(float x, float y) {
    ull r; asm("mov.b64 %0, {%1, %2};" : "=l"(r) : "f"(x), "f"(y)); return r;
}

__global__ void __launch_bounds__(352, 1)
va_main(const float* __restrict__ y, const float* __restrict__ sp, float* __restrict__ out)
{
    extern __shared__ char smem[];
    u32 sb = (u32)__cvta_generic_to_shared(smem);
    int tid = threadIdx.x, wid = tid >> 5, lane = tid & 31;

    if (tid == 0) {
        for (int s = 0; s < NSLOTS; s++) {
            mbar_init(sb + OFF_PF + 8 * s, 64); // 64 fetch lanes arrive
            mbar_init(sb + OFF_PC + 8 * s, 1);  // producer arrives
            mbar_init(sb + OFF_WF + 8 * s, 1);  // producer arrives
            mbar_init(sb + OFF_WE + 8 * s, 8);  // 8 bit-warp leaders arrive
        }
    }
    __syncthreads();

    if (wid == 10) {
        // -------- serial Viterbi producer: HIGHEST wid => wins hi-wid-first
        // arbitration on its SMSP every cycle it is eligible --------
        if (lane == 0) {
            ull w01 = 0ull, w23 = 0ull, w45 = 0ull, w67 = 0ull;
            for (int c = 0; c < NCHUNK; c++) {
                int s = c & 3;
                mbar_wait(sb + OFF_PF + 8 * s, (c >> 2) & 1);
                if (c >= NSLOTS) mbar_wait(sb + OFF_WE + 8 * s, ((c - NSLOTS) >> 2) & 1);
                const ulonglong2* __restrict__ pp =
                    (const ulonglong2*)(smem + OFF_P + s * PSLOT);
                ulonglong2* __restrict__ wp =
                    (ulonglong2*)(smem + OFF_W + s * WSLOT);
                // distance-1 prefetch: q[k+1] loads issue BEFORE step k's math,
                // ~20 issue slots ahead of their consumers -> LDS latency hidden.
                ulonglong2 q0 = pp[0], q1 = pp[1], q2 = pp[2], q3 = pp[3];
                #pragma unroll 8
                for (int k = 0; k < KSTEPS; k++) {
                    ulonglong2 n0 = pp[4 * k + 4];
                    ulonglong2 n1 = pp[4 * k + 5];
                    ulonglong2 n2 = pp[4 * k + 6];
                    ulonglong2 n3 = pp[4 * k + 7];
                    // m[u] = w[u&7] + p[u], packed two-at-a-time
                    ull m0 = addx2(w01, q0.x), m1 = addx2(w23, q0.y);
                    ull m2 = addx2(w45, q1.x), m3 = addx2(w67, q1.y);
                    ull m4 = addx2(w01, q2.x), m5 = addx2(w23, q2.y);
                    ull m6 = addx2(w45, q3.x), m7 = addx2(w67, q3.y);
                    // out[q] = min(m[2q], m[2q+1])  (horizontal within pair)
                    float o0 = fminf(f2lo(m0), f2hi(m0));
                    float o1 = fminf(f2lo(m1), f2hi(m1));
                    float o2 = fminf(f2lo(m2), f2hi(m2));
                    float o3 = fminf(f2lo(m3), f2hi(m3));
                    float o4 = fminf(f2lo(m4), f2hi(m4));
                    float o5 = fminf(f2lo(m5), f2hi(m5));
                    float o6 = fminf(f2lo(m6), f2hi(m6));
                    float o7 = fminf(f2lo(m7), f2hi(m7));
                    w01 = fpack(o0, o1); w23 = fpack(o2, o3);
                    w45 = fpack(o4, o5); w67 = fpack(o6, o7);
                    wp[2 * k + 0] = make_ulonglong2(w01, w23);
                    wp[2 * k + 1] = make_ulonglong2(w45, w67);
                    q0 = n0; q1 = n1; q2 = n2; q3 = n3;
                }
                mbar_arrive(sb + OFF_PC + 8 * s);
                mbar_arrive(sb + OFF_WF + 8 * s);
            }
        }
    } else if (wid < 2) {
        // ---------------- branch-metric producers: p[t][u] = |y[t] - sp[u]| ----
        int base = wid * 32 + lane;         // 0..63
        int quad = base & 3;                // fixed 4-state group per lane
        float s0 = sp[quad * 4 + 0], s1 = sp[quad * 4 + 1];
        float s2 = sp[quad * 4 + 2], s3 = sp[quad * 4 + 3];
        for (int c = 0; c < NCHUNK; c++) {
            int s = c & 3;
            if (c >= NSLOTS) mbar_wait(sb + OFF_PC + 8 * s, ((c - NSLOTS) >> 2) & 1);
            float4* __restrict__ pb = (float4*)(smem + OFF_P + s * PSLOT);
            const float* yc = y + c * KSTEPS;
            #pragma unroll 4
            for (int it = 0; it < 32; it++) {
                int idx = it * 64 + base;
                int k = idx >> 2;           // step within chunk
                float yv = __ldg(&yc[k]);
                pb[k * 4 + quad] = make_float4(fabsf(yv - s0), fabsf(yv - s1),
                                               fabsf(yv - s2), fabsf(yv - s3));
            }
            mbar_arrive(sb + OFF_PF + 8 * s);
        }
    } else {
        // ---------------- bit extractors: bit[t] = argmin(w_t) % 2 -------------
        int btid = tid - 64;                // 0..255 (wid 2..9)
        if (btid == 0) out[0] = 0.0f;       // v_0 = zeros -> argmin = 0 -> bit 0
        const float4* wr = (const float4*)(smem + OFF_W);
        for (int c = 0; c < NCHUNK; c++) {
            int s = c & 3;
            mbar_wait(sb + OFF_WF + 8 * s, (c >> 2) & 1);
            #pragma unroll
            for (int r = 0; r < 2; r++) {
                int k = r * 256 + btid;
                int i = c * KSTEPS + k;     // producer step index; W[i] = w_{i+1}
                if (i != T_LEN - 1) {
                    const float4* p = wr + (size_t)(s * KSTEPS + k) * 2;
                    float4 a = p[0], b = p[1];
                    // first-index argmin over 8 (strict < keeps lowest index,
                    // matching jnp.argmin tie-breaking; w[s]==w[s+8] so 8 suffice)
                    float best = a.x; int bi = 0;
                    if (a.y < best) { best = a.y; bi = 1; }
                    if (a.z < best) { best = a.z; bi = 2; }
                    if (a.w < best) { best = a.w; bi = 3; }
                    if (b.x < best) { best = b.x; bi = 4; }
                    if (b.y < best) { best = b.y; bi = 5; }
                    if (b.z < best) { best = b.z; bi = 6; }
                    if (b.w < best) {            bi = 7; }
                    out[i + 1] = (float)(bi & 1);
                }
            }
            __syncwarp();
            if (lane == 0) mbar_arrive(sb + OFF_WE + 8 * s);
        }
    }
}

extern "C" void kernel_launch(void* const* d_in, const int* in_sizes, int n_in,
                              void* d_out, int out_size)
{
    const float* a = (const float*)d_in[0];
    const float* b = (const float*)d_in[1];
    const float* y;
    const float* sp;
    if (in_sizes[0] == 16) { sp = a; y = b; }
    else                   { y = a;  sp = b; }

    cudaFuncSetAttribute(va_main, cudaFuncAttributeMaxDynamicSharedMemorySize, SMEM_SZ);
    va_main<<<1, 352, SMEM_SZ>>>(y, sp, (float*)d_out);
}

// round 5
// speedup vs baseline: 1.5820x; 1.1426x over previous
#include <cuda_runtime.h>
#include <cstdint>

#define T_LEN   1048576
#define KSTEPS  512
#define NSLOTS  4
#define NCHUNK  (T_LEN / KSTEPS)

// shared memory layout (bytes)
#define OFF_PF   0                         // p_full[4]   (8B each)
#define OFF_PC   32                        // p_cons[4]
#define OFF_WF   64                        // w_full[4]
#define OFF_WE   96                        // w_free[4]
#define OFF_P    256                       // p ring: 4 slots x 512 steps x 64B
#define PSLOT    (KSTEPS * 64)
#define OFF_W    (OFF_P + NSLOTS * PSLOT)  // w ring: 4 slots x 512 steps x 32B
#define WSLOT    (KSTEPS * 32)
#define SMEM_SZ  (OFF_W + NSLOTS * WSLOT + 256)  // pad for prefetch overrun

typedef unsigned int u32;

__device__ __forceinline__ void mbar_init(u32 a, u32 cnt) {
    asm volatile("mbarrier.init.shared.b64 [%0], %1;" :: "r"(a), "r"(cnt) : "memory");
}
__device__ __forceinline__ void mbar_arrive(u32 a) {
    asm volatile("mbarrier.arrive.release.cta.shared::cta.b64 _, [%0];" :: "r"(a) : "memory");
}
__device__ __forceinline__ void mbar_wait(u32 a, u32 par) {
    u32 done;
    asm volatile(
        "{\n\t.reg .pred p;\n\t"
        "mbarrier.try_wait.parity.acquire.cta.shared::cta.b64 p, [%1], %2;\n\t"
        "selp.b32 %0, 1, 0, p;\n\t}"
        : "=r"(done) : "r"(a), "r"(par) : "memory");
    if (!done) {
        asm volatile(
            "{\n\t.reg .pred P1;\n\t"
            "WL_%=:\n\t"
            "mbarrier.try_wait.parity.acquire.cta.shared::cta.b64 P1, [%0], %1, 0x989680;\n\t"
            "@P1 bra.uni WD_%=;\n\t"
            "bra.uni WL_%=;\n\t"
            "WD_%=:\n\t}"
            :: "r"(a), "r"(par) : "memory");
    }
}

__global__ void __launch_bounds__(352, 1)
va_main(const float* __restrict__ y, const float* __restrict__ sp, float* __restrict__ out)
{
    extern __shared__ char smem[];
    u32 sb = (u32)__cvta_generic_to_shared(smem);
    int tid = threadIdx.x, wid = tid >> 5, lane = tid & 31;

    if (tid == 0) {
        for (int s = 0; s < NSLOTS; s++) {
            mbar_init(sb + OFF_PF + 8 * s, 64); // 64 fetch lanes arrive
            mbar_init(sb + OFF_PC + 8 * s, 1);  // producer arrives
            mbar_init(sb + OFF_WF + 8 * s, 1);  // producer arrives
            mbar_init(sb + OFF_WE + 8 * s, 8);  // 8 bit-warp leaders arrive
        }
    }
    __syncthreads();

    if (wid == 10) {
        // -------- serial Viterbi producer: highest wid wins hi-wid-first
        // arbitration on its SMSP. ALL-SCALAR math: float4 loads give 16
        // metrics as individual regs (no unpack movs), FADD/FMNMX write
        // arbitrary regs (no pack movs). --------
        if (lane == 0) {
            float w0 = 0.f, w1 = 0.f, w2 = 0.f, w3 = 0.f;
            float w4 = 0.f, w5 = 0.f, w6 = 0.f, w7 = 0.f;
            for (int c = 0; c < NCHUNK; c++) {
                int s = c & 3;
                mbar_wait(sb + OFF_PF + 8 * s, (c >> 2) & 1);
                if (c >= NSLOTS) mbar_wait(sb + OFF_WE + 8 * s, ((c - NSLOTS) >> 2) & 1);
                const float4* __restrict__ pp =
                    (const float4*)(smem + OFF_P + s * PSLOT);   // 4 float4 per step
                float4* __restrict__ wp =
                    (float4*)(smem + OFF_W + s * WSLOT);         // 2 float4 per step
                // distance-2 prefetch: loads issue ~2 steps (~64 slots) ahead
                // of consumption -> 29-cycle LDS latency fully hidden.
                float4 a0 = pp[0], a1 = pp[1], a2 = pp[2], a3 = pp[3];
                float4 b0 = pp[4], b1 = pp[5], b2 = pp[6], b3 = pp[7];
                #pragma unroll 8
                for (int k = 0; k < KSTEPS; k++) {
                    float4 c0 = pp[4 * k +  8];
                    float4 c1 = pp[4 * k +  9];
                    float4 c2 = pp[4 * k + 10];
                    float4 c3 = pp[4 * k + 11];
                    // m[u] = w[u&7] + p[u]  (16 scalar adds, reference order)
                    float m0  = w0 + a0.x, m1  = w1 + a0.y;
                    float m2  = w2 + a0.z, m3  = w3 + a0.w;
                    float m4  = w4 + a1.x, m5  = w5 + a1.y;
                    float m6  = w6 + a1.z, m7  = w7 + a1.w;
                    float m8  = w0 + a2.x, m9  = w1 + a2.y;
                    float m10 = w2 + a2.z, m11 = w3 + a2.w;
                    float m12 = w4 + a3.x, m13 = w5 + a3.y;
                    float m14 = w6 + a3.z, m15 = w7 + a3.w;
                    // o[q] = min(m[2q], m[2q+1])
                    w0 = fminf(m0,  m1);  w1 = fminf(m2,  m3);
                    w2 = fminf(m4,  m5);  w3 = fminf(m6,  m7);
                    w4 = fminf(m8,  m9);  w5 = fminf(m10, m11);
                    w6 = fminf(m12, m13); w7 = fminf(m14, m15);
                    wp[2 * k + 0] = make_float4(w0, w1, w2, w3);
                    wp[2 * k + 1] = make_float4(w4, w5, w6, w7);
                    a0 = b0; a1 = b1; a2 = b2; a3 = b3;
                    b0 = c0; b1 = c1; b2 = c2; b3 = c3;
                }
                mbar_arrive(sb + OFF_PC + 8 * s);
                mbar_arrive(sb + OFF_WF + 8 * s);
            }
        }
    } else if (wid < 2) {
        // ---------------- branch-metric producers: p[t][u] = |y[t] - sp[u]| ----
        int base = wid * 32 + lane;         // 0..63
        int quad = base & 3;                // fixed 4-state group per lane
        float s0 = sp[quad * 4 + 0], s1 = sp[quad * 4 + 1];
        float s2 = sp[quad * 4 + 2], s3 = sp[quad * 4 + 3];
        for (int c = 0; c < NCHUNK; c++) {
            int s = c & 3;
            if (c >= NSLOTS) mbar_wait(sb + OFF_PC + 8 * s, ((c - NSLOTS) >> 2) & 1);
            float4* __restrict__ pb = (float4*)(smem + OFF_P + s * PSLOT);
            const float* yc = y + c * KSTEPS;
            #pragma unroll 4
            for (int it = 0; it < 32; it++) {
                int idx = it * 64 + base;
                int k = idx >> 2;           // step within chunk
                float yv = __ldg(&yc[k]);
                pb[k * 4 + quad] = make_float4(fabsf(yv - s0), fabsf(yv - s1),
                                               fabsf(yv - s2), fabsf(yv - s3));
            }
            mbar_arrive(sb + OFF_PF + 8 * s);
        }
    } else {
        // ---------------- bit extractors: bit[t] = argmin(w_t) % 2 -------------
        int btid = tid - 64;                // 0..255 (wid 2..9)
        if (btid == 0) out[0] = 0.0f;       // v_0 = zeros -> argmin = 0 -> bit 0
        const float4* wr = (const float4*)(smem + OFF_W);
        for (int c = 0; c < NCHUNK; c++) {
            int s = c & 3;
            mbar_wait(sb + OFF_WF + 8 * s, (c >> 2) & 1);
            #pragma unroll
            for (int r = 0; r < 2; r++) {
                int k = r * 256 + btid;
                int i = c * KSTEPS + k;     // producer step index; W[i] = w_{i+1}
                if (i != T_LEN - 1) {
                    const float4* p = wr + (size_t)(s * KSTEPS + k) * 2;
                    float4 a = p[0], b = p[1];
                    // first-index argmin over 8 (strict < keeps lowest index,
                    // matching jnp.argmin tie-breaking; w[s]==w[s+8] so 8 suffice)
                    float best = a.x; int bi = 0;
                    if (a.y < best) { best = a.y; bi = 1; }
                    if (a.z < best) { best = a.z; bi = 2; }
                    if (a.w < best) { best = a.w; bi = 3; }
                    if (b.x < best) { best = b.x; bi = 4; }
                    if (b.y < best) { best = b.y; bi = 5; }
                    if (b.z < best) { best = b.z; bi = 6; }
                    if (b.w < best) {            bi = 7; }
                    out[i + 1] = (float)(bi & 1);
                }
            }
            __syncwarp();
            if (lane == 0) mbar_arrive(sb + OFF_WE + 8 * s);
        }
    }
}

extern "C" void kernel_launch(void* const* d_in, const int* in_sizes, int n_in,
                              void* d_out, int out_size)
{
    const float* a = (const float*)d_in[0];
    const float* b = (const float*)d_in[1];
    const float* y;
    const float* sp;
    if (in_sizes[0] == 16) { sp = a; y = b; }
    else                   { y = a;  sp = b; }

    cudaFuncSetAttribute(va_main, cudaFuncAttributeMaxDynamicSharedMemorySize, SMEM_SZ);
    va_main<<<1, 352, SMEM_SZ>>>(y, sp, (float*)d_out);
}

// round 6
// speedup vs baseline: 1.7137x; 1.0832x over previous
#include <cuda_runtime.h>
#include <cstdint>

#define T_LEN   1048576
#define KSTEPS  512
#define NSLOTS  4
#define NCHUNK  (T_LEN / KSTEPS)

// shared memory layout (bytes)
#define OFF_PF   0                         // p_full[4]   (8B each)
#define OFF_PC   32                        // p_cons[4]
#define OFF_WF   64                        // w_full[4]
#define OFF_WE   96                        // w_free[4]
#define OFF_P    256                       // p ring: 4 slots x 512 steps x 64B
#define PSLOT    (KSTEPS * 64)
#define OFF_W    (OFF_P + NSLOTS * PSLOT)  // w ring: 4 slots x 512 steps x 32B
#define WSLOT    (KSTEPS * 32)
#define SMEM_SZ  (OFF_W + NSLOTS * WSLOT + 256)  // pad for prefetch overrun

typedef unsigned int u32;

__device__ __forceinline__ void mbar_init(u32 a, u32 cnt) {
    asm volatile("mbarrier.init.shared.b64 [%0], %1;" :: "r"(a), "r"(cnt) : "memory");
}
__device__ __forceinline__ void mbar_arrive(u32 a) {
    asm volatile("mbarrier.arrive.release.cta.shared::cta.b64 _, [%0];" :: "r"(a) : "memory");
}
__device__ __forceinline__ void mbar_wait(u32 a, u32 par) {
    u32 done;
    asm volatile(
        "{\n\t.reg .pred p;\n\t"
        "mbarrier.try_wait.parity.acquire.cta.shared::cta.b64 p, [%1], %2;\n\t"
        "selp.b32 %0, 1, 0, p;\n\t}"
        : "=r"(done) : "r"(a), "r"(par) : "memory");
    if (!done) {
        asm volatile(
            "{\n\t.reg .pred P1;\n\t"
            "WL_%=:\n\t"
            "mbarrier.try_wait.parity.acquire.cta.shared::cta.b64 P1, [%0], %1, 0x989680;\n\t"
            "@P1 bra.uni WD_%=;\n\t"
            "bra.uni WL_%=;\n\t"
            "WD_%=:\n\t}"
            :: "r"(a), "r"(par) : "memory");
    }
}

// w + p via fma(w, 1.0, p): bit-exact (x*1.0 exact, single rounding), but the
// immediate-multiplier FFMA form has rt_SMSP=1 vs FADD's 2 -> 2x fma-pipe tput.
// Non-volatile so ptxas schedules freely; asm stops nvcc folding it to add.
__device__ __forceinline__ float fadd_ffma(float w, float p) {
    float r;
    asm("fma.rn.f32 %0, %1, 0f3F800000, %2;" : "=f"(r) : "f"(w), "f"(p));
    return r;
}

__global__ void __launch_bounds__(352, 1)
va_main(const float* __restrict__ y, const float* __restrict__ sp, float* __restrict__ out)
{
    extern __shared__ char smem[];
    u32 sb = (u32)__cvta_generic_to_shared(smem);
    int tid = threadIdx.x, wid = tid >> 5, lane = tid & 31;

    if (tid == 0) {
        for (int s = 0; s < NSLOTS; s++) {
            mbar_init(sb + OFF_PF + 8 * s, 64); // 64 fetch lanes arrive
            mbar_init(sb + OFF_PC + 8 * s, 1);  // producer arrives
            mbar_init(sb + OFF_WF + 8 * s, 1);  // producer arrives
            mbar_init(sb + OFF_WE + 8 * s, 8);  // 8 bit-warp leaders arrive
        }
    }
    __syncthreads();

    if (wid == 10) {
        // -------- serial Viterbi producer (highest wid: wins hi-wid-first
        // arbitration). FFMA-imm adds (rt 1) + FMNMX (alu pipe) balance the
        // two pipes; MIO ops spread between math groups to dodge LDS->LDS /
        // STS->STS structural floors. --------
        if (lane == 0) {
            float w0 = 0.f, w1 = 0.f, w2 = 0.f, w3 = 0.f;
            float w4 = 0.f, w5 = 0.f, w6 = 0.f, w7 = 0.f;
            for (int c = 0; c < NCHUNK; c++) {
                int s = c & 3;
                mbar_wait(sb + OFF_PF + 8 * s, (c >> 2) & 1);
                if (c >= NSLOTS) mbar_wait(sb + OFF_WE + 8 * s, ((c - NSLOTS) >> 2) & 1);
                const float4* __restrict__ pp =
                    (const float4*)(smem + OFF_P + s * PSLOT);   // 4 float4 per step
                float4* __restrict__ wp =
                    (float4*)(smem + OFF_W + s * WSLOT);         // 2 float4 per step
                // distance-2 prefetch
                float4 a0 = pp[0], a1 = pp[1], a2 = pp[2], a3 = pp[3];
                float4 b0 = pp[4], b1 = pp[5], b2 = pp[6], b3 = pp[7];
                #pragma unroll 16
                for (int k = 0; k < KSTEPS; k++) {
                    // prefetch loads interleaved with math groups
                    float4 c0 = pp[4 * k + 8];
                    float m0  = fadd_ffma(w0, a0.x), m1  = fadd_ffma(w1, a0.y);
                    float m2  = fadd_ffma(w2, a0.z), m3  = fadd_ffma(w3, a0.w);
                    float4 c1 = pp[4 * k + 9];
                    float m4  = fadd_ffma(w4, a1.x), m5  = fadd_ffma(w5, a1.y);
                    float m6  = fadd_ffma(w6, a1.z), m7  = fadd_ffma(w7, a1.w);
                    float4 c2 = pp[4 * k + 10];
                    float m8  = fadd_ffma(w0, a2.x), m9  = fadd_ffma(w1, a2.y);
                    float m10 = fadd_ffma(w2, a2.z), m11 = fadd_ffma(w3, a2.w);
                    float4 c3 = pp[4 * k + 11];
                    float m12 = fadd_ffma(w4, a3.x), m13 = fadd_ffma(w5, a3.y);
                    float m14 = fadd_ffma(w6, a3.z), m15 = fadd_ffma(w7, a3.w);
                    // o[q] = min(m[2q], m[2q+1])
                    w0 = fminf(m0,  m1);  w1 = fminf(m2,  m3);
                    w2 = fminf(m4,  m5);  w3 = fminf(m6,  m7);
                    wp[2 * k + 0] = make_float4(w0, w1, w2, w3);
                    w4 = fminf(m8,  m9);  w5 = fminf(m10, m11);
                    w6 = fminf(m12, m13); w7 = fminf(m14, m15);
                    wp[2 * k + 1] = make_float4(w4, w5, w6, w7);
                    a0 = b0; a1 = b1; a2 = b2; a3 = b3;
                    b0 = c0; b1 = c1; b2 = c2; b3 = c3;
                }
                mbar_arrive(sb + OFF_PC + 8 * s);
                mbar_arrive(sb + OFF_WF + 8 * s);
            }
        }
    } else if (wid < 2) {
        // ---------------- branch-metric producers: p[t][u] = |y[t] - sp[u]| ----
        int base = wid * 32 + lane;         // 0..63
        int quad = base & 3;                // fixed 4-state group per lane
        float s0 = sp[quad * 4 + 0], s1 = sp[quad * 4 + 1];
        float s2 = sp[quad * 4 + 2], s3 = sp[quad * 4 + 3];
        for (int c = 0; c < NCHUNK; c++) {
            int s = c & 3;
            if (c >= NSLOTS) mbar_wait(sb + OFF_PC + 8 * s, ((c - NSLOTS) >> 2) & 1);
            float4* __restrict__ pb = (float4*)(smem + OFF_P + s * PSLOT);
            const float* yc = y + c * KSTEPS;
            #pragma unroll 4
            for (int it = 0; it < 32; it++) {
                int idx = it * 64 + base;
                int k = idx >> 2;           // step within chunk
                float yv = __ldg(&yc[k]);
                pb[k * 4 + quad] = make_float4(fabsf(yv - s0), fabsf(yv - s1),
                                               fabsf(yv - s2), fabsf(yv - s3));
            }
            mbar_arrive(sb + OFF_PF + 8 * s);
        }
    } else {
        // ---------------- bit extractors: bit[t] = argmin(w_t) % 2 -------------
        int btid = tid - 64;                // 0..255 (wid 2..9)
        if (btid == 0) out[0] = 0.0f;       // v_0 = zeros -> argmin = 0 -> bit 0
        const float4* wr = (const float4*)(smem + OFF_W);
        for (int c = 0; c < NCHUNK; c++) {
            int s = c & 3;
            mbar_wait(sb + OFF_WF + 8 * s, (c >> 2) & 1);
            #pragma unroll
            for (int r = 0; r < 2; r++) {
                int k = r * 256 + btid;
                int i = c * KSTEPS + k;     // producer step index; W[i] = w_{i+1}
                if (i != T_LEN - 1) {
                    const float4* p = wr + (size_t)(s * KSTEPS + k) * 2;
                    float4 a = p[0], b = p[1];
                    // first-index argmin over 8 (strict < keeps lowest index,
                    // matching jnp.argmin tie-breaking; w[s]==w[s+8] so 8 suffice)
                    float best = a.x; int bi = 0;
                    if (a.y < best) { best = a.y; bi = 1; }
                    if (a.z < best) { best = a.z; bi = 2; }
                    if (a.w < best) { best = a.w; bi = 3; }
                    if (b.x < best) { best = b.x; bi = 4; }
                    if (b.y < best) { best = b.y; bi = 5; }
                    if (b.z < best) { best = b.z; bi = 6; }
                    if (b.w < best) {            bi = 7; }
                    out[i + 1] = (float)(bi & 1);
                }
            }
            __syncwarp();
            if (lane == 0) mbar_arrive(sb + OFF_WE + 8 * s);
        }
    }
}

extern "C" void kernel_launch(void* const* d_in, const int* in_sizes, int n_in,
                              void* d_out, int out_size)
{
    const float* a = (const float*)d_in[0];
    const float* b = (const float*)d_in[1];
    const float* y;
    const float* sp;
    if (in_sizes[0] == 16) { sp = a; y = b; }
    else                   { y = a;  sp = b; }

    cudaFuncSetAttribute(va_main, cudaFuncAttributeMaxDynamicSharedMemorySize, SMEM_SZ);
    va_main<<<1, 352, SMEM_SZ>>>(y, sp, (float*)d_out);
}

// round 7
// speedup vs baseline: 1.7446x; 1.0180x over previous
#include <cuda_runtime.h>
#include <cstdint>

#define T_LEN   1048576
#define KSTEPS  512
#define NSLOTS  4
#define NCHUNK  (T_LEN / KSTEPS)

// shared memory layout (bytes)
#define OFF_PF   0                         // p_full[4]   (8B each)
#define OFF_PC   32                        // p_cons[4]
#define OFF_WF   64                        // w_full[4]
#define OFF_WE   96                        // w_free[4]
#define OFF_P    256                       // p ring: 4 slots x 512 steps x 64B
#define PSLOT    (KSTEPS * 64)
#define OFF_W    (OFF_P + NSLOTS * PSLOT)  // w ring: 4 slots x 512 steps x 32B
#define WSLOT    (KSTEPS * 32)
#define SMEM_SZ  (OFF_W + NSLOTS * WSLOT + 256)  // pad for prefetch overrun

typedef unsigned long long ull;
typedef unsigned int u32;

__device__ __forceinline__ void mbar_init(u32 a, u32 cnt) {
    asm volatile("mbarrier.init.shared.b64 [%0], %1;" :: "r"(a), "r"(cnt) : "memory");
}
__device__ __forceinline__ void mbar_arrive(u32 a) {
    asm volatile("mbarrier.arrive.release.cta.shared::cta.b64 _, [%0];" :: "r"(a) : "memory");
}
__device__ __forceinline__ void mbar_wait(u32 a, u32 par) {
    u32 done;
    asm volatile(
        "{\n\t.reg .pred p;\n\t"
        "mbarrier.try_wait.parity.acquire.cta.shared::cta.b64 p, [%1], %2;\n\t"
        "selp.b32 %0, 1, 0, p;\n\t}"
        : "=r"(done) : "r"(a), "r"(par) : "memory");
    if (!done) {
        asm volatile(
            "{\n\t.reg .pred P1;\n\t"
            "WL_%=:\n\t"
            "mbarrier.try_wait.parity.acquire.cta.shared::cta.b64 P1, [%0], %1, 0x989680;\n\t"
            "@P1 bra.uni WD_%=;\n\t"
            "bra.uni WL_%=;\n\t"
            "WD_%=:\n\t}"
            :: "r"(a), "r"(par) : "memory");
    }
}

// packed fma: (a.lo*1+c.lo, a.hi*1+c.hi) -- two bit-exact IEEE-rn adds, ONE instr.
__device__ __forceinline__ ull fma2(ull a, ull one2, ull c) {
    ull r; asm("fma.rn.f32x2 %0, %1, %2, %3;" : "=l"(r) : "l"(a), "l"(one2), "l"(c));
    return r;
}
// pack/unpack in C++ (mov.b64 {lo,hi}): ptxas resolves via register allocation,
// NOT real MOVs (unlike asm-boundary operands).
__device__ __forceinline__ ull fpack2(float lo, float hi) {
    union { float f[2]; ull u; } v; v.f[0] = lo; v.f[1] = hi; return v.u;
}
__device__ __forceinline__ float flo(ull x) {
    union { ull u; float f[2]; } v; v.u = x; return v.f[0];
}
__device__ __forceinline__ float fhi(ull x) {
    union { ull u; float f[2]; } v; v.u = x; return v.f[1];
}

__global__ void __launch_bounds__(352, 1)
va_main(const float* __restrict__ y, const float* __restrict__ sp, float* __restrict__ out)
{
    extern __shared__ char smem[];
    u32 sb = (u32)__cvta_generic_to_shared(smem);
    int tid = threadIdx.x, wid = tid >> 5, lane = tid & 31;

    if (tid == 0) {
        for (int s = 0; s < NSLOTS; s++) {
            mbar_init(sb + OFF_PF + 8 * s, 64); // 64 fetch lanes arrive
            mbar_init(sb + OFF_PC + 8 * s, 1);  // producer arrives
            mbar_init(sb + OFF_WF + 8 * s, 1);  // producer arrives
            mbar_init(sb + OFF_WE + 8 * s, 8);  // 8 bit-warp leaders arrive
        }
    }
    __syncthreads();

    if (wid == 10) {
        // -------- serial Viterbi producer (highest wid wins arbitration).
        // Split-pair layout: E0=(w0,w2) O0=(w1,w3) E1=(w4,w6) O1=(w5,w7).
        // 8 packed FFMA2 do all 16 adds; 8 scalar FMNMX read pair components
        // directly (no unpack); export order == pair layout (no repack). ----
        if (lane == 0) {
            ull E0 = 0ull, O0 = 0ull, E1 = 0ull, O1 = 0ull;
            const ull one2 = fpack2(1.0f, 1.0f);
            for (int c = 0; c < NCHUNK; c++) {
                int s = c & 3;
                mbar_wait(sb + OFF_PF + 8 * s, (c >> 2) & 1);
                if (c >= NSLOTS) mbar_wait(sb + OFF_WE + 8 * s, ((c - NSLOTS) >> 2) & 1);
                const ulonglong2* __restrict__ pp =
                    (const ulonglong2*)(smem + OFF_P + s * PSLOT);   // 4 per step
                float4* __restrict__ wp =
                    (float4*)(smem + OFF_W + s * WSLOT);             // 2 per step
                // distance-2 prefetch (ring has +256B pad for the overrun)
                ulonglong2 a0 = pp[0], a1 = pp[1], a2 = pp[2], a3 = pp[3];
                ulonglong2 b0 = pp[4], b1 = pp[5], b2 = pp[6], b3 = pp[7];
                #pragma unroll 16
                for (int k = 0; k < KSTEPS; k++) {
                    ulonglong2 c0 = pp[4 * k +  8];
                    // a_.x = (p_e0,p_e1) even pair, a_.y = odd pair (helper layout)
                    ull mEa = fma2(E0, one2, a0.x);   // (m0,  m2)
                    ull mOa = fma2(O0, one2, a0.y);   // (m1,  m3)
                    ulonglong2 c1 = pp[4 * k +  9];
                    ull mEb = fma2(E1, one2, a1.x);   // (m4,  m6)
                    ull mOb = fma2(O1, one2, a1.y);   // (m5,  m7)
                    ulonglong2 c2 = pp[4 * k + 10];
                    ull mEc = fma2(E0, one2, a2.x);   // (m8,  m10)
                    ull mOc = fma2(O0, one2, a2.y);   // (m9,  m11)
                    ulonglong2 c3 = pp[4 * k + 11];
                    ull mEd = fma2(E1, one2, a3.x);   // (m12, m14)
                    ull mOd = fma2(O1, one2, a3.y);   // (m13, m15)
                    // o[q] = min(m[2q], m[2q+1]) -- scalar mins on components
                    float o0 = fminf(flo(mEa), flo(mOa));
                    float o1 = fminf(fhi(mEa), fhi(mOa));
                    float o2 = fminf(flo(mEb), flo(mOb));
                    float o3 = fminf(fhi(mEb), fhi(mOb));
                    float o4 = fminf(flo(mEc), flo(mOc));
                    float o5 = fminf(fhi(mEc), fhi(mOc));
                    float o6 = fminf(flo(mEd), flo(mOd));
                    float o7 = fminf(fhi(mEd), fhi(mOd));
                    // export in split order (bit warps un-permute for free)
                    wp[2 * k + 0] = make_float4(o0, o2, o1, o3);
                    wp[2 * k + 1] = make_float4(o4, o6, o5, o7);
                    E0 = fpack2(o0, o2); O0 = fpack2(o1, o3);
                    E1 = fpack2(o4, o6); O1 = fpack2(o5, o7);
                    a0 = b0; a1 = b1; a2 = b2; a3 = b3;
                    b0 = c0; b1 = c1; b2 = c2; b3 = c3;
                }
                mbar_arrive(sb + OFF_PC + 8 * s);
                mbar_arrive(sb + OFF_WF + 8 * s);
            }
        }
    } else if (wid < 2) {
        // -------- branch-metric producers: p[t][u] = |y[t] - sp[u]|,
        // written in split-pair order (4q, 4q+2, 4q+1, 4q+3) --------
        int base = wid * 32 + lane;         // 0..63
        int quad = base & 3;                // fixed 4-state group per lane
        float s0 = sp[quad * 4 + 0], s1 = sp[quad * 4 + 2];
        float s2 = sp[quad * 4 + 1], s3 = sp[quad * 4 + 3];
        for (int c = 0; c < NCHUNK; c++) {
            int s = c & 3;
            if (c >= NSLOTS) mbar_wait(sb + OFF_PC + 8 * s, ((c - NSLOTS) >> 2) & 1);
            float4* __restrict__ pb = (float4*)(smem + OFF_P + s * PSLOT);
            const float* yc = y + c * KSTEPS;
            #pragma unroll 4
            for (int it = 0; it < 32; it++) {
                int idx = it * 64 + base;
                int k = idx >> 2;           // step within chunk
                float yv = __ldg(&yc[k]);
                pb[k * 4 + quad] = make_float4(fabsf(yv - s0), fabsf(yv - s1),
                                               fabsf(yv - s2), fabsf(yv - s3));
            }
            mbar_arrive(sb + OFF_PF + 8 * s);
        }
    } else {
        // -------- bit extractors: bit[t] = argmin(w_t) % 2.
        // W stored split-pair: mem = (o0,o2,o1,o3, o4,o6,o5,o7); scan in
        // LOGICAL index order o0,o1,...,o7 (strict < = first-index ties,
        // matching jnp.argmin over the duplicated 16-vector). --------
        int btid = tid - 64;                // 0..255 (wid 2..9)
        if (btid == 0) out[0] = 0.0f;       // v_0 = zeros -> argmin = 0 -> bit 0
        const float4* wr = (const float4*)(smem + OFF_W);
        for (int c = 0; c < NCHUNK; c++) {
            int s = c & 3;
            mbar_wait(sb + OFF_WF + 8 * s, (c >> 2) & 1);
            #pragma unroll
            for (int r = 0; r < 2; r++) {
                int k = r * 256 + btid;
                int i = c * KSTEPS + k;     // producer step index; W[i] = w_{i+1}
                if (i != T_LEN - 1) {
                    const float4* p = wr + (size_t)(s * KSTEPS + k) * 2;
                    float4 a = p[0], b = p[1];
                    // logical order: o0=a.x o1=a.z o2=a.y o3=a.w
                    //                o4=b.x o5=b.z o6=b.y o7=b.w
                    float best = a.x; int bi = 0;        // o0
                    if (a.z < best) { best = a.z; bi = 1; }  // o1
                    if (a.y < best) { best = a.y; bi = 2; }  // o2
                    if (a.w < best) { best = a.w; bi = 3; }  // o3
                    if (b.x < best) { best = b.x; bi = 4; }  // o4
                    if (b.z < best) { best = b.z; bi = 5; }  // o5
                    if (b.y < best) { best = b.y; bi = 6; }  // o6
                    if (b.w < best) {            bi = 7; }   // o7
                    out[i + 1] = (float)(bi & 1);
                }
            }
            __syncwarp();
            if (lane == 0) mbar_arrive(sb + OFF_WE + 8 * s);
        }
    }
}

extern "C" void kernel_launch(void* const* d_in, const int* in_sizes, int n_in,
                              void* d_out, int out_size)
{
    const float* a = (const float*)d_in[0];
    const float* b = (const float*)d_in[1];
    const float* y;
    const float* sp;
    if (in_sizes[0] == 16) { sp = a; y = b; }
    else                   { y = a;  sp = b; }

    cudaFuncSetAttribute(va_main, cudaFuncAttributeMaxDynamicSharedMemorySize, SMEM_SZ);
    va_main<<<1, 352, SMEM_SZ>>>(y, sp, (float*)d_out);
}